// round 1
// baseline (speedup 1.0000x reference)
#include <cuda_runtime.h>
#include <math.h>

#define B 4
#define S 2048
#define SE 2048
#define DM 1024
#define H 16
#define DP 64
#define DFF 4096
#define M_TOK (B*S)          // 8192
#define EPS 1e-6f

// ---------------- static scratch (no allocations allowed) ----------------
__device__ float g_q[M_TOK*DM];
__device__ float g_k[M_TOK*DM];
__device__ float g_v[M_TOK*DM];
__device__ float g_ctx[M_TOK*DM];
__device__ float g_out1[M_TOK*DM];
__device__ float g_out2[M_TOK*DM];
__device__ float g_tmp[M_TOK*DM];
__device__ float g_ffn[M_TOK*DFF];
__device__ float g_sc[268435456];   // B*H*S*S scores/probs scratch (1.07 GB)

// ---------------- dense GEMM: C[M,N] = A[M,K] @ W[K,N] + bias (+ReLU) ----
// 128x128 block tile, 8x8 per thread, 256 threads, BK=8
__global__ __launch_bounds__(256) void sgemm_bias(
    const float* __restrict__ A, const float* __restrict__ W,
    const float* __restrict__ bias, float* __restrict__ C,
    int Mdim, int Ndim, int Kdim, int relu)
{
    __shared__ float As[8][128];
    __shared__ float Ws[8][128];
    const int tid = threadIdx.x;
    const int tx = tid & 15, ty = tid >> 4;
    const int row0 = blockIdx.y * 128;
    const int col0 = blockIdx.x * 128;

    const int aRow = tid >> 1;          // 0..127
    const int aCol = (tid & 1) * 4;     // 0 or 4
    const int wRow = tid >> 5;          // 0..7
    const int wCol = (tid & 31) * 4;    // 0..124

    float acc[8][8];
    #pragma unroll
    for (int i = 0; i < 8; i++)
        #pragma unroll
        for (int j = 0; j < 8; j++) acc[i][j] = 0.f;

    const float* Aptr = A + (size_t)(row0 + aRow) * Kdim + aCol;
    const float* Wptr = W + (size_t)wRow * Ndim + col0 + wCol;

    for (int k0 = 0; k0 < Kdim; k0 += 8) {
        float4 av = *(const float4*)(Aptr + k0);
        As[aCol + 0][aRow] = av.x; As[aCol + 1][aRow] = av.y;
        As[aCol + 2][aRow] = av.z; As[aCol + 3][aRow] = av.w;
        float4 wv = *(const float4*)(Wptr + (size_t)k0 * Ndim);
        *(float4*)&Ws[wRow][wCol] = wv;
        __syncthreads();

        #pragma unroll
        for (int kk = 0; kk < 8; kk++) {
            float4 a0 = *(const float4*)&As[kk][ty * 8];
            float4 a1 = *(const float4*)&As[kk][ty * 8 + 4];
            float4 b0 = *(const float4*)&Ws[kk][tx * 8];
            float4 b1 = *(const float4*)&Ws[kk][tx * 8 + 4];
            float a[8] = {a0.x,a0.y,a0.z,a0.w,a1.x,a1.y,a1.z,a1.w};
            float b[8] = {b0.x,b0.y,b0.z,b0.w,b1.x,b1.y,b1.z,b1.w};
            #pragma unroll
            for (int i = 0; i < 8; i++)
                #pragma unroll
                for (int j = 0; j < 8; j++)
                    acc[i][j] = fmaf(a[i], b[j], acc[i][j]);
        }
        __syncthreads();
    }

    #pragma unroll
    for (int i = 0; i < 8; i++) {
        const int r = row0 + ty * 8 + i;
        float* Crow = C + (size_t)r * Ndim + col0 + tx * 8;
        #pragma unroll
        for (int j = 0; j < 8; j += 4) {
            float4 bv = *(const float4*)(bias + col0 + tx * 8 + j);
            float4 o;
            o.x = acc[i][j+0] + bv.x; o.y = acc[i][j+1] + bv.y;
            o.z = acc[i][j+2] + bv.z; o.w = acc[i][j+3] + bv.w;
            if (relu) {
                o.x = fmaxf(o.x, 0.f); o.y = fmaxf(o.y, 0.f);
                o.z = fmaxf(o.z, 0.f); o.w = fmaxf(o.w, 0.f);
            }
            *(float4*)(Crow + j) = o;
        }
    }
}

// ---------------- attention scores: out[bh,q,k] = Q.K^T/8 + mask*-1e9 ----
// mode 0: look-ahead mask [B,1,S,S]; mode 1: padding mask [B,1,1,SE]
__global__ __launch_bounds__(256) void scores_kernel(
    const float* __restrict__ Q, const float* __restrict__ Kmat,
    const float* __restrict__ mask, float* __restrict__ out, int mode)
{
    __shared__ float Qs[64][68];   // [d][q]
    __shared__ float Ks[64][68];   // [d][k]
    const int tid = threadIdx.x;
    const int bh = blockIdx.z, b = bh >> 4, h = bh & 15;
    const int q0 = blockIdx.y * 64, k0 = blockIdx.x * 64;
    const float* Qb = Q   + ((size_t)b * S + q0) * DM + h * DP;
    const float* Kb = Kmat + ((size_t)b * S + k0) * DM + h * DP;

    const int r = tid >> 4;           // 0..15
    const int c = (tid & 15) * 4;     // 0..60
    #pragma unroll
    for (int rr = r; rr < 64; rr += 16) {
        float4 qv = *(const float4*)(Qb + (size_t)rr * DM + c);
        Qs[c+0][rr] = qv.x; Qs[c+1][rr] = qv.y; Qs[c+2][rr] = qv.z; Qs[c+3][rr] = qv.w;
        float4 kv = *(const float4*)(Kb + (size_t)rr * DM + c);
        Ks[c+0][rr] = kv.x; Ks[c+1][rr] = kv.y; Ks[c+2][rr] = kv.z; Ks[c+3][rr] = kv.w;
    }
    __syncthreads();

    const int tx = tid & 15, ty = tid >> 4;
    float acc[4][4] = {};
    #pragma unroll
    for (int kk = 0; kk < 64; kk++) {
        float4 a = *(const float4*)&Qs[kk][ty * 4];
        float4 v = *(const float4*)&Ks[kk][tx * 4];
        float av[4] = {a.x,a.y,a.z,a.w};
        float bv[4] = {v.x,v.y,v.z,v.w};
        #pragma unroll
        for (int i = 0; i < 4; i++)
            #pragma unroll
            for (int j = 0; j < 4; j++)
                acc[i][j] = fmaf(av[i], bv[j], acc[i][j]);
    }

    #pragma unroll
    for (int i = 0; i < 4; i++) {
        const int q = q0 + ty * 4 + i;
        float* orow = out + ((size_t)bh * S + q) * S + k0 + tx * 4;
        float4 o;
        float m0, m1, m2, m3;
        if (mode == 0) {
            const float* mrow = mask + ((size_t)b * S + q) * S + k0 + tx * 4;
            m0 = mrow[0]; m1 = mrow[1]; m2 = mrow[2]; m3 = mrow[3];
        } else {
            const float* mrow = mask + (size_t)b * SE + k0 + tx * 4;
            m0 = mrow[0]; m1 = mrow[1]; m2 = mrow[2]; m3 = mrow[3];
        }
        o.x = acc[i][0] * 0.125f + m0 * (-1e9f);
        o.y = acc[i][1] * 0.125f + m1 * (-1e9f);
        o.z = acc[i][2] * 0.125f + m2 * (-1e9f);
        o.w = acc[i][3] * 0.125f + m3 * (-1e9f);
        *(float4*)orow = o;
    }
}

// ---------------- row softmax over S=2048, one block per row --------------
__global__ __launch_bounds__(256) void softmax_kernel(
    const float* __restrict__ src, float* __restrict__ dst)
{
    const size_t row = blockIdx.x;
    const float* p = src + row * (size_t)S;
    float* o = dst + row * (size_t)S;
    const int tid = threadIdx.x;
    const int lane = tid & 31, warp = tid >> 5;
    __shared__ float red_max[8];
    __shared__ float red_sum[8];

    float v[8];
    float mx = -INFINITY;
    #pragma unroll
    for (int i = 0; i < 8; i++) { v[i] = p[tid + i * 256]; mx = fmaxf(mx, v[i]); }
    #pragma unroll
    for (int off = 16; off; off >>= 1) mx = fmaxf(mx, __shfl_xor_sync(0xffffffffu, mx, off));
    if (lane == 0) red_max[warp] = mx;
    __syncthreads();
    mx = red_max[0];
    #pragma unroll
    for (int w = 1; w < 8; w++) mx = fmaxf(mx, red_max[w]);

    float sum = 0.f;
    #pragma unroll
    for (int i = 0; i < 8; i++) { v[i] = __expf(v[i] - mx); sum += v[i]; }
    #pragma unroll
    for (int off = 16; off; off >>= 1) sum += __shfl_xor_sync(0xffffffffu, sum, off);
    if (lane == 0) red_sum[warp] = sum;
    __syncthreads();
    sum = 0.f;
    #pragma unroll
    for (int w = 0; w < 8; w++) sum += red_sum[w];
    const float inv = 1.f / sum;
    #pragma unroll
    for (int i = 0; i < 8; i++) o[tid + i * 256] = v[i] * inv;
}

// ---------------- attn @ V: out[b,q,h*64+d] = sum_k P[bh,q,k] V[b,k,h*64+d]
__global__ __launch_bounds__(256) void av_kernel(
    const float* __restrict__ P, const float* __restrict__ V,
    float* __restrict__ out)
{
    __shared__ float Ps[64][68];   // [k][q]
    __shared__ float Vs[64][68];   // [k][d]
    const int tid = threadIdx.x;
    const int bh = blockIdx.z, b = bh >> 4, h = bh & 15;
    const int q0 = blockIdx.y * 64;
    const float* Pb = P + ((size_t)bh * S + q0) * S;
    const float* Vb = V + (size_t)b * S * DM + h * DP;

    const int tx = tid & 15, ty = tid >> 4;
    const int r = tid >> 4;
    const int c = (tid & 15) * 4;
    float acc[4][4] = {};

    for (int kc = 0; kc < S; kc += 64) {
        #pragma unroll
        for (int rr = r; rr < 64; rr += 16) {
            float4 pv = *(const float4*)(Pb + (size_t)rr * S + kc + c);
            Ps[c+0][rr] = pv.x; Ps[c+1][rr] = pv.y; Ps[c+2][rr] = pv.z; Ps[c+3][rr] = pv.w;
            float4 vv = *(const float4*)(Vb + (size_t)(kc + rr) * DM + c);
            *(float4*)&Vs[rr][c] = vv;
        }
        __syncthreads();
        #pragma unroll
        for (int kk = 0; kk < 64; kk++) {
            float4 a = *(const float4*)&Ps[kk][ty * 4];
            float4 v = *(const float4*)&Vs[kk][tx * 4];
            float av[4] = {a.x,a.y,a.z,a.w};
            float bv[4] = {v.x,v.y,v.z,v.w};
            #pragma unroll
            for (int i = 0; i < 4; i++)
                #pragma unroll
                for (int j = 0; j < 4; j++)
                    acc[i][j] = fmaf(av[i], bv[j], acc[i][j]);
        }
        __syncthreads();
    }

    #pragma unroll
    for (int i = 0; i < 4; i++) {
        const int q = q0 + ty * 4 + i;
        float4 o = {acc[i][0], acc[i][1], acc[i][2], acc[i][3]};
        *(float4*)(out + ((size_t)b * S + q) * DM + h * DP + tx * 4) = o;
    }
}

// ---------------- fused residual add + LayerNorm (rows of 1024) ----------
__global__ __launch_bounds__(256) void add_ln_kernel(
    const float* __restrict__ a, const float* __restrict__ bres,
    const float* __restrict__ g, const float* __restrict__ beta,
    float* __restrict__ out)
{
    const size_t row = blockIdx.x;
    const float* pa = a + row * DM;
    const float* pb = bres + row * DM;
    const int tid = threadIdx.x;
    const int lane = tid & 31, warp = tid >> 5;
    __shared__ float red_s[8];
    __shared__ float red_s2[8];

    float x[4];
    float s = 0.f, s2 = 0.f;
    #pragma unroll
    for (int i = 0; i < 4; i++) {
        float t = pa[tid + i * 256] + pb[tid + i * 256];
        x[i] = t; s += t; s2 += t * t;
    }
    #pragma unroll
    for (int off = 16; off; off >>= 1) {
        s  += __shfl_xor_sync(0xffffffffu, s, off);
        s2 += __shfl_xor_sync(0xffffffffu, s2, off);
    }
    if (lane == 0) { red_s[warp] = s; red_s2[warp] = s2; }
    __syncthreads();
    s = 0.f; s2 = 0.f;
    #pragma unroll
    for (int w = 0; w < 8; w++) { s += red_s[w]; s2 += red_s2[w]; }

    const float mu = s * (1.f / DM);
    const float var = s2 * (1.f / DM) - mu * mu;
    const float inv = rsqrtf(var + EPS);
    #pragma unroll
    for (int i = 0; i < 4; i++) {
        const int col = tid + i * 256;
        out[row * DM + col] = (x[i] - mu) * inv * g[col] + beta[col];
    }
}

// ------------------------------- launch -----------------------------------
extern "C" void kernel_launch(void* const* d_in, const int* in_sizes, int n_in,
                              void* d_out, int out_size)
{
    const float* x    = (const float*)d_in[0];
    const float* enc  = (const float*)d_in[1];
    const float* lam  = (const float*)d_in[2];
    const float* pm   = (const float*)d_in[3];
    const float* wq1  = (const float*)d_in[4];  const float* bq1 = (const float*)d_in[5];
    const float* wk1  = (const float*)d_in[6];  const float* bk1 = (const float*)d_in[7];
    const float* wv1  = (const float*)d_in[8];  const float* bv1 = (const float*)d_in[9];
    const float* wo1  = (const float*)d_in[10]; const float* bo1 = (const float*)d_in[11];
    const float* wq2  = (const float*)d_in[12]; const float* bq2 = (const float*)d_in[13];
    const float* wk2  = (const float*)d_in[14]; const float* bk2 = (const float*)d_in[15];
    const float* wv2  = (const float*)d_in[16]; const float* bv2 = (const float*)d_in[17];
    const float* wo2  = (const float*)d_in[18]; const float* bo2 = (const float*)d_in[19];
    const float* wf1  = (const float*)d_in[20]; const float* bf1 = (const float*)d_in[21];
    const float* wf2  = (const float*)d_in[22]; const float* bf2 = (const float*)d_in[23];
    const float* ln2g = (const float*)d_in[24]; const float* ln2b = (const float*)d_in[25];
    const float* ln3g = (const float*)d_in[26]; const float* ln3b = (const float*)d_in[27];

    float* out3    = (float*)d_out;
    float* logits2 = (float*)d_out + (size_t)M_TOK * DM;

    float *q, *k, *v, *ctx, *out1, *out2, *tmp, *ffn, *sc;
    cudaGetSymbolAddress((void**)&q,    g_q);
    cudaGetSymbolAddress((void**)&k,    g_k);
    cudaGetSymbolAddress((void**)&v,    g_v);
    cudaGetSymbolAddress((void**)&ctx,  g_ctx);
    cudaGetSymbolAddress((void**)&out1, g_out1);
    cudaGetSymbolAddress((void**)&out2, g_out2);
    cudaGetSymbolAddress((void**)&tmp,  g_tmp);
    cudaGetSymbolAddress((void**)&ffn,  g_ffn);
    cudaGetSymbolAddress((void**)&sc,   g_sc);

    const dim3 gD(DM / 128, M_TOK / 128);     // 1024-wide GEMMs
    const dim3 gF(DFF / 128, M_TOK / 128);    // 4096-wide GEMM
    const dim3 gS(S / 64, S / 64, B * H);     // score tiles
    const dim3 gA(1, S / 64, B * H);          // AV tiles

    // ---- MHA1 (self-attention, out1 = attn1, no LN/residual) ----
    sgemm_bias<<<gD, 256>>>(x, wq1, bq1, q, M_TOK, DM, DM, 0);
    sgemm_bias<<<gD, 256>>>(x, wk1, bk1, k, M_TOK, DM, DM, 0);
    sgemm_bias<<<gD, 256>>>(x, wv1, bv1, v, M_TOK, DM, DM, 0);
    scores_kernel<<<gS, 256>>>(q, k, lam, sc, 0);
    softmax_kernel<<<B * H * S, 256>>>(sc, sc);
    av_kernel<<<gA, 256>>>(sc, v, ctx);
    sgemm_bias<<<gD, 256>>>(ctx, wo1, bo1, out1, M_TOK, DM, DM, 0);

    // ---- MHA2 (cross-attention; logits2 is an output) ----
    sgemm_bias<<<gD, 256>>>(out1, wq2, bq2, q, M_TOK, DM, DM, 0);
    sgemm_bias<<<gD, 256>>>(enc,  wk2, bk2, k, M_TOK, DM, DM, 0);
    sgemm_bias<<<gD, 256>>>(enc,  wv2, bv2, v, M_TOK, DM, DM, 0);
    scores_kernel<<<gS, 256>>>(q, k, pm, logits2, 1);
    softmax_kernel<<<B * H * S, 256>>>(logits2, sc);
    av_kernel<<<gA, 256>>>(sc, v, ctx);
    sgemm_bias<<<gD, 256>>>(ctx, wo2, bo2, tmp, M_TOK, DM, DM, 0);
    add_ln_kernel<<<M_TOK, 256>>>(tmp, out1, ln2g, ln2b, out2);

    // ---- FFN + LN3 ----
    sgemm_bias<<<gF, 256>>>(out2, wf1, bf1, ffn, M_TOK, DFF, DM, 1);
    sgemm_bias<<<gD, 256>>>(ffn, wf2, bf2, tmp, M_TOK, DM, DFF, 0);
    add_ln_kernel<<<M_TOK, 256>>>(tmp, out2, ln3g, ln3b, out3);
}

// round 4
// speedup vs baseline: 1.7934x; 1.7934x over previous
#include <cuda_runtime.h>
#include <cuda_bf16.h>
#include <math.h>

typedef __nv_bfloat16 bf16;

#define NB 4
#define S 2048
#define DM 1024
#define NH 16
#define DP 64
#define DFF 4096
#define MT (NB*S)      // 8192
#define BH (NB*NH)     // 64
#define EPS 1e-6f

// ---------------- static scratch (~1.79 GB total) ----------------
__device__ float g_q[MT*DM];                    // 32MB
__device__ float g_k[MT*DM];
__device__ float g_v[MT*DM];
__device__ float g_ctx[MT*DM];
__device__ float g_out1[MT*DM];
__device__ float g_out2[MT*DM];
__device__ float g_tmp[MT*DM];
__device__ float g_ffn[(size_t)MT*DFF];         // 128MB
__device__ float g_sp[(size_t)BH*S*S];          // 1073MB: fp32 logits (MHA1) / bf16 [Ph|Pl] probs union
__device__ bf16  g_ab[(size_t)MT*3*DFF];        // 192MB: A' split activations
__device__ bf16  g_wt[(size_t)DFF*3*DM];        // 24MB: W' transposed split
__device__ bf16  g_qs[(size_t)BH*S*192];        // 48MB: Q split per head
__device__ bf16  g_ks[(size_t)BH*S*192];        // 48MB: K split per head
__device__ bf16  g_vs[(size_t)BH*DP*3*S];       // 48MB: V^T split per head [hi|lo|hi]

// ---------------- helpers ----------------
__device__ __forceinline__ unsigned bpack(bf16 a, bf16 b) {
    unsigned short ua = *reinterpret_cast<unsigned short*>(&a);
    unsigned short ub = *reinterpret_cast<unsigned short*>(&b);
    return (unsigned)ua | ((unsigned)ub << 16);
}
__device__ __forceinline__ void split1(float x, bf16& h, bf16& l) {
    h = __float2bfloat16_rn(x);
    l = __float2bfloat16_rn(x - __bfloat162float(h));
}
__device__ __forceinline__ void cp16(void* smem, const void* g) {
    unsigned s = (unsigned)__cvta_generic_to_shared(smem);
    asm volatile("cp.async.cg.shared.global [%0], [%1], 16;\n" :: "r"(s), "l"(g));
}
#define CP_COMMIT asm volatile("cp.async.commit_group;\n" ::)
#define CP_WAIT0  asm volatile("cp.async.wait_group 0;\n" ::)

__device__ __forceinline__ void mma16816(float* c, const unsigned* a, const unsigned* b) {
    asm volatile(
        "mma.sync.aligned.m16n8k16.row.col.f32.bf16.bf16.f32 "
        "{%0,%1,%2,%3}, {%4,%5,%6,%7}, {%8,%9}, {%0,%1,%2,%3};\n"
        : "+f"(c[0]), "+f"(c[1]), "+f"(c[2]), "+f"(c[3])
        : "r"(a[0]), "r"(a[1]), "r"(a[2]), "r"(a[3]), "r"(b[0]), "r"(b[1]));
}

// warp computes (MI*16) x (NI*8) for one 32-wide k-chunk; LD = smem row stride
template<int MI, int NI, int LD>
__device__ __forceinline__ void wmma_ks(const bf16* As, const bf16* Bs, int lane,
                                        float acc[MI][NI][4])
{
    const int g = lane >> 2, t2 = (lane & 3) * 2;
    #pragma unroll
    for (int ks = 0; ks < 32; ks += 16) {
        unsigned a[MI][4], bb[NI][2];
        #pragma unroll
        for (int mi = 0; mi < MI; mi++) {
            const bf16* p = As + (mi*16 + g) * LD + ks + t2;
            a[mi][0] = *(const unsigned*)p;
            a[mi][1] = *(const unsigned*)(p + 8*LD);
            a[mi][2] = *(const unsigned*)(p + 8);
            a[mi][3] = *(const unsigned*)(p + 8*LD + 8);
        }
        #pragma unroll
        for (int ni = 0; ni < NI; ni++) {
            const bf16* p = Bs + (ni*8 + g) * LD + ks + t2;
            bb[ni][0] = *(const unsigned*)p;
            bb[ni][1] = *(const unsigned*)(p + 8);
        }
        #pragma unroll
        for (int mi = 0; mi < MI; mi++)
            #pragma unroll
            for (int ni = 0; ni < NI; ni++)
                mma16816(acc[mi][ni], a[mi], bb[ni]);
    }
}

__device__ __forceinline__ void ld_tile128(bf16* sm, const bf16* gp, size_t ldg, int tid) {
    const int r = tid >> 2, c = (tid & 3) * 8;
    cp16(sm + r*40 + c,      gp + (size_t)r * ldg + c);
    cp16(sm + (r+64)*40 + c, gp + (size_t)(r+64) * ldg + c);
}
__device__ __forceinline__ void ld_tile64(bf16* sm, const bf16* gp, size_t ldg, int tid) {
    const int r = tid >> 2, c = (tid & 3) * 8;
    cp16(sm + r*40 + c, gp + (size_t)r * ldg + c);
}

// ---------------- conversion kernels ----------------
// fp32 [M,K] -> bf16 [M,3K] = [hi | hi | lo]
__global__ __launch_bounds__(256) void split_rows(
    const float* __restrict__ in, bf16* __restrict__ out, int K)
{
    int id = blockIdx.x * 256 + threadIdx.x;
    int kq = K >> 2;
    int row = id / kq, c4 = id - row * kq;
    float4 v = ((const float4*)in)[(size_t)row * kq + c4];
    bf16 h0,h1,h2,h3,l0,l1,l2,l3;
    split1(v.x,h0,l0); split1(v.y,h1,l1); split1(v.z,h2,l2); split1(v.w,h3,l3);
    uint2 hp = {bpack(h0,h1), bpack(h2,h3)};
    uint2 lp = {bpack(l0,l1), bpack(l2,l3)};
    size_t base = (size_t)row * 3 * K + c4 * 4;
    *(uint2*)(out + base)       = hp;
    *(uint2*)(out + base + K)   = hp;
    *(uint2*)(out + base + 2*K) = lp;
}

// fp32 W[K,N] -> bf16 Wt[N,3K] = [hi | lo | hi]  (transposed)
__global__ void split_wt(const float* __restrict__ W, bf16* __restrict__ Wt,
                         int K, int N)
{
    __shared__ float t[32][33];
    int k0 = blockIdx.y * 32, n0 = blockIdx.x * 32;
    int tx = threadIdx.x, ty = threadIdx.y;
    #pragma unroll
    for (int j = 0; j < 4; j++)
        t[ty + j*8][tx] = W[(size_t)(k0 + ty + j*8) * N + n0 + tx];
    __syncthreads();
    int K3 = 3 * K;
    #pragma unroll
    for (int j = 0; j < 4; j++) {
        int n = n0 + ty + j*8, k = k0 + tx;
        bf16 h, l; split1(t[tx][ty + j*8], h, l);
        Wt[(size_t)n*K3 + k]       = h;
        Wt[(size_t)n*K3 + K + k]   = l;
        Wt[(size_t)n*K3 + 2*K + k] = h;
    }
}

// fp32 [b*S+q][h*64+d] -> bf16 [bh][q][192]; side0=[hi,hi,lo] side1=[hi,lo,hi]
__global__ __launch_bounds__(256) void split_qk(
    const float* __restrict__ in, bf16* __restrict__ out, int side)
{
    int id = blockIdx.x * 256 + threadIdx.x;
    int row = id >> 8, c4 = id & 255;
    float4 v = ((const float4*)in)[(size_t)row * 256 + c4];
    int col = c4 * 4, h = col >> 6, d = col & 63;
    int b = row >> 11, q = row & 2047;
    bf16 h0,h1,h2,h3,l0,l1,l2,l3;
    split1(v.x,h0,l0); split1(v.y,h1,l1); split1(v.z,h2,l2); split1(v.w,h3,l3);
    uint2 hp = {bpack(h0,h1), bpack(h2,h3)};
    uint2 lp = {bpack(l0,l1), bpack(l2,l3)};
    size_t base = ((size_t)((b*NH + h)*S + q)) * 192 + d;
    if (side == 0) {
        *(uint2*)(out + base)       = hp;
        *(uint2*)(out + base + 64)  = hp;
        *(uint2*)(out + base + 128) = lp;
    } else {
        *(uint2*)(out + base)       = hp;
        *(uint2*)(out + base + 64)  = lp;
        *(uint2*)(out + base + 128) = hp;
    }
}

// fp32 V [b*S+k][h*64+d] -> bf16 Vs[bh][d][3*2048] = [hi | lo | hi]
__global__ void split_v(const float* __restrict__ v, bf16* __restrict__ vs)
{
    __shared__ float t[32][33];
    int k0 = blockIdx.x * 32, d0 = blockIdx.y * 32, bh = blockIdx.z;
    int b = bh >> 4, h = bh & 15;
    int tx = threadIdx.x, ty = threadIdx.y;
    #pragma unroll
    for (int j = 0; j < 4; j++)
        t[ty + j*8][tx] = v[(size_t)(b*S + k0 + ty + j*8)*DM + h*64 + d0 + tx];
    __syncthreads();
    #pragma unroll
    for (int j = 0; j < 4; j++) {
        int d = d0 + ty + j*8, k = k0 + tx;
        bf16 hi, lo; split1(t[tx][ty + j*8], hi, lo);
        size_t base = ((size_t)bh*64 + d) * (3*S) + k;
        vs[base]       = hi;
        vs[base + S]   = lo;
        vs[base + 2*S] = hi;
    }
}

// ---------------- dense GEMM: C[M,N] = A'[M,3K] . Wt'[N,3K]^T + bias ------
__global__ __launch_bounds__(256) void hgemm_bias(
    const bf16* __restrict__ A, const bf16* __restrict__ Bt,
    const float* __restrict__ bias, float* __restrict__ C,
    int Nd, int K3, int relu)
{
    __shared__ bf16 As[2][128*40];
    __shared__ bf16 Bs[2][128*40];
    const int tid = threadIdx.x, lane = tid & 31, warp = tid >> 5;
    const int wm = warp >> 2, wn = warp & 3;
    const int m0 = blockIdx.y * 128, n0 = blockIdx.x * 128;
    const bf16* Ag = A  + (size_t)m0 * K3;
    const bf16* Bg = Bt + (size_t)n0 * K3;
    float acc[4][4][4] = {};
    const int KT = K3 >> 5;

    ld_tile128(As[0], Ag, K3, tid);
    ld_tile128(Bs[0], Bg, K3, tid);
    CP_COMMIT;
    for (int kt = 0; kt < KT; kt++) {
        CP_WAIT0; __syncthreads();
        if (kt + 1 < KT) {
            const int st = (kt + 1) & 1;
            ld_tile128(As[st], Ag + (size_t)(kt+1)*32, K3, tid);
            ld_tile128(Bs[st], Bg + (size_t)(kt+1)*32, K3, tid);
            CP_COMMIT;
        }
        wmma_ks<4,4,40>(&As[kt&1][wm*64*40], &Bs[kt&1][wn*32*40], lane, acc);
    }

    const int g = lane >> 2, t2 = (lane & 3) * 2;
    #pragma unroll
    for (int mi = 0; mi < 4; mi++)
        #pragma unroll
        for (int ni = 0; ni < 4; ni++) {
            const int r = m0 + wm*64 + mi*16 + g;
            const int c = n0 + wn*32 + ni*8 + t2;
            float2 bv = *(const float2*)(bias + c);
            float2 o1 = {acc[mi][ni][0] + bv.x, acc[mi][ni][1] + bv.y};
            float2 o2 = {acc[mi][ni][2] + bv.x, acc[mi][ni][3] + bv.y};
            if (relu) {
                o1.x = fmaxf(o1.x, 0.f); o1.y = fmaxf(o1.y, 0.f);
                o2.x = fmaxf(o2.x, 0.f); o2.y = fmaxf(o2.y, 0.f);
            }
            *(float2*)(C + (size_t)r*Nd + c)     = o1;
            *(float2*)(C + (size_t)(r+8)*Nd + c) = o2;
        }
}

// ---------------- scores: logits[bh,q,k] = Q'.K'^T/8 + mask*-1e9 ----------
__global__ __launch_bounds__(256) void hscores(
    const bf16* __restrict__ Qs, const bf16* __restrict__ Ks,
    const float* __restrict__ mask, float* __restrict__ out, int mode)
{
    __shared__ bf16 As[2][128*40];
    __shared__ bf16 Bs[2][128*40];
    const int tid = threadIdx.x, lane = tid & 31, warp = tid >> 5;
    const int wm = warp >> 2, wn = warp & 3;
    const int bh = blockIdx.z, b = bh >> 4;
    const int q0 = blockIdx.y * 128, k0 = blockIdx.x * 128;
    const bf16* Ag = Qs + ((size_t)bh*S + q0) * 192;
    const bf16* Bg = Ks + ((size_t)bh*S + k0) * 192;
    float acc[4][4][4] = {};

    ld_tile128(As[0], Ag, 192, tid);
    ld_tile128(Bs[0], Bg, 192, tid);
    CP_COMMIT;
    #pragma unroll
    for (int kt = 0; kt < 6; kt++) {
        CP_WAIT0; __syncthreads();
        if (kt + 1 < 6) {
            const int st = (kt + 1) & 1;
            ld_tile128(As[st], Ag + (kt+1)*32, 192, tid);
            ld_tile128(Bs[st], Bg + (kt+1)*32, 192, tid);
            CP_COMMIT;
        }
        wmma_ks<4,4,40>(&As[kt&1][wm*64*40], &Bs[kt&1][wn*32*40], lane, acc);
    }

    const int g = lane >> 2, t2 = (lane & 3) * 2;
    #pragma unroll
    for (int mi = 0; mi < 4; mi++)
        #pragma unroll
        for (int ni = 0; ni < 4; ni++) {
            const int q = q0 + wm*64 + mi*16 + g;
            const int k = k0 + wn*32 + ni*8 + t2;
            float2 mA, mB;
            if (mode == 0) {
                mA = *(const float2*)(mask + ((size_t)b*S + q)*S + k);
                mB = *(const float2*)(mask + ((size_t)b*S + q + 8)*S + k);
            } else {
                mA = *(const float2*)(mask + (size_t)b*S + k);
                mB = mA;
            }
            float2 o1 = {acc[mi][ni][0]*0.125f + mA.x*(-1e9f),
                         acc[mi][ni][1]*0.125f + mA.y*(-1e9f)};
            float2 o2 = {acc[mi][ni][2]*0.125f + mB.x*(-1e9f),
                         acc[mi][ni][3]*0.125f + mB.y*(-1e9f)};
            *(float2*)(out + ((size_t)bh*S + q)*S + k)     = o1;
            *(float2*)(out + ((size_t)bh*S + q + 8)*S + k) = o2;
        }
}

// ---------------- softmax; writes bf16 [Ph(S) | Pl(S)] per row ------------
// In-place capable (dst bytes == src bytes): all loads complete before the
// first __syncthreads, all stores happen after the last one.
__global__ __launch_bounds__(256) void softmax_split(
    const float* src, bf16* dst)
{
    const size_t row = blockIdx.x;
    const float* p = src + row * (size_t)S;
    bf16* oh = dst + row * (size_t)(2*S);
    const int tid = threadIdx.x, lane = tid & 31, warp = tid >> 5;
    __shared__ float rm[8], rs[8];

    float2 v[4];
    float mx = -INFINITY;
    #pragma unroll
    for (int i = 0; i < 4; i++) {
        v[i] = *(const float2*)(p + (size_t)(tid + i*256)*2);
        mx = fmaxf(mx, fmaxf(v[i].x, v[i].y));
    }
    #pragma unroll
    for (int off = 16; off; off >>= 1) mx = fmaxf(mx, __shfl_xor_sync(~0u, mx, off));
    if (lane == 0) rm[warp] = mx;
    __syncthreads();
    mx = rm[0];
    #pragma unroll
    for (int w = 1; w < 8; w++) mx = fmaxf(mx, rm[w]);

    float sum = 0.f;
    #pragma unroll
    for (int i = 0; i < 4; i++) {
        v[i].x = __expf(v[i].x - mx); v[i].y = __expf(v[i].y - mx);
        sum += v[i].x + v[i].y;
    }
    #pragma unroll
    for (int off = 16; off; off >>= 1) sum += __shfl_xor_sync(~0u, sum, off);
    if (lane == 0) rs[warp] = sum;
    __syncthreads();
    sum = 0.f;
    #pragma unroll
    for (int w = 0; w < 8; w++) sum += rs[w];
    const float inv = 1.f / sum;

    #pragma unroll
    for (int i = 0; i < 4; i++) {
        const int c = (tid + i*256) * 2;
        float a = v[i].x * inv, d = v[i].y * inv;
        bf16 ha, la, hd, ldd; split1(a, ha, la); split1(d, hd, ldd);
        *(unsigned*)(oh + c)     = bpack(ha, hd);
        *(unsigned*)(oh + S + c) = bpack(la, ldd);
    }
}

// ---------------- AV: ctx = Ph.Vh + Ph.Vl + Pl.Vh --------------------------
// P rows: [Ph(S)|Pl(S)] stride 2S. Vs rows: [Vh(S)|Vl(S)|Vh(S)] stride 3S.
__global__ __launch_bounds__(256) void hav(
    const bf16* __restrict__ P, const bf16* __restrict__ Vs,
    float* __restrict__ ctx)
{
    __shared__ bf16 As[2][128*40];
    __shared__ bf16 Bs[2][64*40];
    const int tid = threadIdx.x, lane = tid & 31, warp = tid >> 5;
    const int wm = warp >> 1, wn = warp & 1;
    const int bh = blockIdx.z, b = bh >> 4, h = bh & 15;
    const int q0 = blockIdx.y * 128;
    const bf16* Pb = P  + ((size_t)bh*S + q0) * (2*S);
    const bf16* Bg = Vs + (size_t)bh * 64 * (3*S);
    float acc[2][4][4] = {};
    const int KT = 192;   // 3S / 32

    ld_tile128(As[0], Pb, 2*S, tid);
    ld_tile64 (Bs[0], Bg, 3*S, tid);
    CP_COMMIT;
    for (int kt = 0; kt < KT; kt++) {
        CP_WAIT0; __syncthreads();
        if (kt + 1 < KT) {
            const int st = (kt + 1) & 1;
            const int nk = kt + 1;
            const int seg = nk >> 6;                 // 0:Ph.Vh 1:Ph.Vl 2:Pl.Vh
            const int within = (nk & 63) * 32;
            const bf16* Ap = Pb + (seg == 2 ? S : 0) + within;
            ld_tile128(As[st], Ap, 2*S, tid);
            ld_tile64 (Bs[st], Bg + (size_t)nk*32, 3*S, tid);
            CP_COMMIT;
        }
        wmma_ks<2,4,40>(&As[kt&1][wm*32*40], &Bs[kt&1][wn*32*40], lane, acc);
    }

    const int g = lane >> 2, t2 = (lane & 3) * 2;
    #pragma unroll
    for (int mi = 0; mi < 2; mi++)
        #pragma unroll
        for (int ni = 0; ni < 4; ni++) {
            const int q = q0 + wm*32 + mi*16 + g;
            const int d = wn*32 + ni*8 + t2;
            size_t base = ((size_t)b*S + q)*DM + h*64 + d;
            *(float2*)(ctx + base)        = make_float2(acc[mi][ni][0], acc[mi][ni][1]);
            *(float2*)(ctx + base + 8*DM) = make_float2(acc[mi][ni][2], acc[mi][ni][3]);
        }
}

// ---------------- fused residual add + LayerNorm --------------------------
__global__ __launch_bounds__(256) void add_ln_kernel(
    const float* __restrict__ a, const float* __restrict__ bres,
    const float* __restrict__ g, const float* __restrict__ beta,
    float* __restrict__ out)
{
    const size_t row = blockIdx.x;
    const float* pa = a + row * DM;
    const float* pb = bres + row * DM;
    const int tid = threadIdx.x, lane = tid & 31, warp = tid >> 5;
    __shared__ float rs1[8], rs2[8];

    float x[4];
    float s = 0.f, s2 = 0.f;
    #pragma unroll
    for (int i = 0; i < 4; i++) {
        float t = pa[tid + i*256] + pb[tid + i*256];
        x[i] = t; s += t; s2 += t * t;
    }
    #pragma unroll
    for (int off = 16; off; off >>= 1) {
        s  += __shfl_xor_sync(~0u, s, off);
        s2 += __shfl_xor_sync(~0u, s2, off);
    }
    if (lane == 0) { rs1[warp] = s; rs2[warp] = s2; }
    __syncthreads();
    s = 0.f; s2 = 0.f;
    #pragma unroll
    for (int w = 0; w < 8; w++) { s += rs1[w]; s2 += rs2[w]; }
    const float mu = s * (1.f / DM);
    const float var = s2 * (1.f / DM) - mu * mu;
    const float inv = rsqrtf(var + EPS);
    #pragma unroll
    for (int i = 0; i < 4; i++) {
        const int col = tid + i*256;
        out[row*DM + col] = (x[i] - mu) * inv * g[col] + beta[col];
    }
}

// ------------------------------- launch -----------------------------------
extern "C" void kernel_launch(void* const* d_in, const int* in_sizes, int n_in,
                              void* d_out, int out_size)
{
    const float* x    = (const float*)d_in[0];
    const float* enc  = (const float*)d_in[1];
    const float* lam  = (const float*)d_in[2];
    const float* pm   = (const float*)d_in[3];
    const float* wq1  = (const float*)d_in[4];  const float* bq1 = (const float*)d_in[5];
    const float* wk1  = (const float*)d_in[6];  const float* bk1 = (const float*)d_in[7];
    const float* wv1  = (const float*)d_in[8];  const float* bv1 = (const float*)d_in[9];
    const float* wo1  = (const float*)d_in[10]; const float* bo1 = (const float*)d_in[11];
    const float* wq2  = (const float*)d_in[12]; const float* bq2 = (const float*)d_in[13];
    const float* wk2  = (const float*)d_in[14]; const float* bk2 = (const float*)d_in[15];
    const float* wv2  = (const float*)d_in[16]; const float* bv2 = (const float*)d_in[17];
    const float* wo2  = (const float*)d_in[18]; const float* bo2 = (const float*)d_in[19];
    const float* wf1  = (const float*)d_in[20]; const float* bf1 = (const float*)d_in[21];
    const float* wf2  = (const float*)d_in[22]; const float* bf2 = (const float*)d_in[23];
    const float* ln2g = (const float*)d_in[24]; const float* ln2b = (const float*)d_in[25];
    const float* ln3g = (const float*)d_in[26]; const float* ln3b = (const float*)d_in[27];

    float* out3    = (float*)d_out;
    float* logits2 = (float*)d_out + (size_t)MT * DM;

    float *q, *k, *v, *ctx, *out1, *out2, *tmp, *ffn, *sp;
    bf16 *ab, *wt, *qs, *ks, *vs;
    cudaGetSymbolAddress((void**)&q,    g_q);
    cudaGetSymbolAddress((void**)&k,    g_k);
    cudaGetSymbolAddress((void**)&v,    g_v);
    cudaGetSymbolAddress((void**)&ctx,  g_ctx);
    cudaGetSymbolAddress((void**)&out1, g_out1);
    cudaGetSymbolAddress((void**)&out2, g_out2);
    cudaGetSymbolAddress((void**)&tmp,  g_tmp);
    cudaGetSymbolAddress((void**)&ffn,  g_ffn);
    cudaGetSymbolAddress((void**)&sp,   g_sp);
    cudaGetSymbolAddress((void**)&ab,   g_ab);
    cudaGetSymbolAddress((void**)&wt,   g_wt);
    cudaGetSymbolAddress((void**)&qs,   g_qs);
    cudaGetSymbolAddress((void**)&ks,   g_ks);
    cudaGetSymbolAddress((void**)&vs,   g_vs);
    bf16* probs = (bf16*)sp;   // [BH*S][2S] = [Ph|Pl] rows, aliases g_sp bytes

    const dim3 tWT(32, 8);
    const dim3 gWT_dd(DM/32, DM/32);
    const dim3 gWT_df(DFF/32, DM/32);
    const dim3 gWT_fd(DM/32, DFF/32);
    const dim3 gG_d(DM/128, MT/128);
    const dim3 gG_f(DFF/128, MT/128);
    const dim3 gSC(S/128, S/128, BH);
    const dim3 gAV(1, S/128, BH);
    const dim3 gSV(S/32, DP/32, BH);
    const int nSR_d = MT*DM/1024;
    const int nSR_f = (int)((size_t)MT*DFF/1024);

    // ===== MHA1 =====
    split_rows<<<nSR_d, 256>>>(x, ab, DM);
    split_wt<<<gWT_dd, tWT>>>(wq1, wt, DM, DM);
    hgemm_bias<<<gG_d, 256>>>(ab, wt, bq1, q, DM, 3*DM, 0);
    split_wt<<<gWT_dd, tWT>>>(wk1, wt, DM, DM);
    hgemm_bias<<<gG_d, 256>>>(ab, wt, bk1, k, DM, 3*DM, 0);
    split_wt<<<gWT_dd, tWT>>>(wv1, wt, DM, DM);
    hgemm_bias<<<gG_d, 256>>>(ab, wt, bv1, v, DM, 3*DM, 0);
    split_qk<<<MT, 256>>>(q, qs, 0);
    split_qk<<<MT, 256>>>(k, ks, 1);
    split_v<<<gSV, tWT>>>(v, vs);
    hscores<<<gSC, 256>>>(qs, ks, lam, sp, 0);
    softmax_split<<<BH*S, 256>>>(sp, probs);       // in-place fp32 -> [Ph|Pl]
    hav<<<gAV, 256>>>(probs, vs, ctx);
    split_rows<<<nSR_d, 256>>>(ctx, ab, DM);
    split_wt<<<gWT_dd, tWT>>>(wo1, wt, DM, DM);
    hgemm_bias<<<gG_d, 256>>>(ab, wt, bo1, out1, DM, 3*DM, 0);

    // ===== MHA2 (logits2 -> d_out, preserved) =====
    split_rows<<<nSR_d, 256>>>(out1, ab, DM);
    split_wt<<<gWT_dd, tWT>>>(wq2, wt, DM, DM);
    hgemm_bias<<<gG_d, 256>>>(ab, wt, bq2, q, DM, 3*DM, 0);
    split_rows<<<nSR_d, 256>>>(enc, ab, DM);
    split_wt<<<gWT_dd, tWT>>>(wk2, wt, DM, DM);
    hgemm_bias<<<gG_d, 256>>>(ab, wt, bk2, k, DM, 3*DM, 0);
    split_wt<<<gWT_dd, tWT>>>(wv2, wt, DM, DM);
    hgemm_bias<<<gG_d, 256>>>(ab, wt, bv2, v, DM, 3*DM, 0);
    split_qk<<<MT, 256>>>(q, qs, 0);
    split_qk<<<MT, 256>>>(k, ks, 1);
    split_v<<<gSV, tWT>>>(v, vs);
    hscores<<<gSC, 256>>>(qs, ks, pm, logits2, 1);
    softmax_split<<<BH*S, 256>>>(logits2, probs);  // out-of-place
    hav<<<gAV, 256>>>(probs, vs, ctx);
    split_rows<<<nSR_d, 256>>>(ctx, ab, DM);
    split_wt<<<gWT_dd, tWT>>>(wo2, wt, DM, DM);
    hgemm_bias<<<gG_d, 256>>>(ab, wt, bo2, tmp, DM, 3*DM, 0);
    add_ln_kernel<<<MT, 256>>>(tmp, out1, ln2g, ln2b, out2);

    // ===== FFN =====
    split_rows<<<nSR_d, 256>>>(out2, ab, DM);
    split_wt<<<gWT_df, tWT>>>(wf1, wt, DM, DFF);
    hgemm_bias<<<gG_f, 256>>>(ab, wt, bf1, ffn, DFF, 3*DM, 1);
    split_rows<<<nSR_f, 256>>>(ffn, ab, DFF);
    split_wt<<<gWT_fd, tWT>>>(wf2, wt, DFF, DM);
    hgemm_bias<<<gG_d, 256>>>(ab, wt, bf2, tmp, DM, 3*DFF, 0);
    add_ln_kernel<<<MT, 256>>>(tmp, out2, ln3g, ln3b, out3);
}

// round 5
// speedup vs baseline: 2.1892x; 1.2207x over previous
#include <cuda_runtime.h>
#include <cuda_bf16.h>
#include <math.h>

typedef __nv_bfloat16 bf16;

#define NB 4
#define S 2048
#define DM 1024
#define NH 16
#define DP 64
#define DFF 4096
#define MT (NB*S)      // 8192
#define BH (NB*NH)     // 64
#define EPS 1e-6f

// ---------------- static scratch (~0.72 GB total) ----------------
__device__ float g_q[MT*DM];
__device__ float g_k[MT*DM];
__device__ float g_v[MT*DM];
__device__ float g_ctx[MT*DM];
__device__ float g_out1[MT*DM];
__device__ float g_out2[MT*DM];
__device__ float g_tmp[MT*DM];
__device__ float g_ffn[(size_t)MT*DFF];         // 128MB
__device__ bf16  g_ab[(size_t)MT*3*DFF];        // 192MB: A' split activations
__device__ bf16  g_wt[(size_t)DFF*3*DM];        // 24MB: W' transposed split
__device__ bf16  g_qs[(size_t)BH*S*192];        // 48MB: Q split [hi,hi,lo]
__device__ bf16  g_ks[(size_t)BH*S*192];        // 48MB: K split [hi,lo,hi]
__device__ bf16  g_vs[(size_t)BH*DP*3*S];       // 48MB: V^T split [hi|lo|hi]

// ---------------- helpers ----------------
__device__ __forceinline__ unsigned bpack(bf16 a, bf16 b) {
    unsigned short ua = *reinterpret_cast<unsigned short*>(&a);
    unsigned short ub = *reinterpret_cast<unsigned short*>(&b);
    return (unsigned)ua | ((unsigned)ub << 16);
}
__device__ __forceinline__ void split1(float x, bf16& h, bf16& l) {
    h = __float2bfloat16_rn(x);
    l = __float2bfloat16_rn(x - __bfloat162float(h));
}
__device__ __forceinline__ void cp16(void* smem, const void* g) {
    unsigned s = (unsigned)__cvta_generic_to_shared(smem);
    asm volatile("cp.async.cg.shared.global [%0], [%1], 16;\n" :: "r"(s), "l"(g));
}
#define CP_COMMIT asm volatile("cp.async.commit_group;\n" ::)
#define CP_WAIT0  asm volatile("cp.async.wait_group 0;\n" ::)

__device__ __forceinline__ void mma16816(float* c, const unsigned* a, const unsigned* b) {
    asm volatile(
        "mma.sync.aligned.m16n8k16.row.col.f32.bf16.bf16.f32 "
        "{%0,%1,%2,%3}, {%4,%5,%6,%7}, {%8,%9}, {%0,%1,%2,%3};\n"
        : "+f"(c[0]), "+f"(c[1]), "+f"(c[2]), "+f"(c[3])
        : "r"(a[0]), "r"(a[1]), "r"(a[2]), "r"(a[3]), "r"(b[0]), "r"(b[1]));
}

// warp computes (MI*16) x (NI*8) for one 32-wide k-chunk; LD = smem row stride
template<int MI, int NI, int LD>
__device__ __forceinline__ void wmma_ks(const bf16* As, const bf16* Bs, int lane,
                                        float acc[MI][NI][4])
{
    const int g = lane >> 2, t2 = (lane & 3) * 2;
    #pragma unroll
    for (int ks = 0; ks < 32; ks += 16) {
        unsigned a[MI][4], bb[NI][2];
        #pragma unroll
        for (int mi = 0; mi < MI; mi++) {
            const bf16* p = As + (mi*16 + g) * LD + ks + t2;
            a[mi][0] = *(const unsigned*)p;
            a[mi][1] = *(const unsigned*)(p + 8*LD);
            a[mi][2] = *(const unsigned*)(p + 8);
            a[mi][3] = *(const unsigned*)(p + 8*LD + 8);
        }
        #pragma unroll
        for (int ni = 0; ni < NI; ni++) {
            const bf16* p = Bs + (ni*8 + g) * LD + ks + t2;
            bb[ni][0] = *(const unsigned*)p;
            bb[ni][1] = *(const unsigned*)(p + 8);
        }
        #pragma unroll
        for (int mi = 0; mi < MI; mi++)
            #pragma unroll
            for (int ni = 0; ni < NI; ni++)
                mma16816(acc[mi][ni], a[mi], bb[ni]);
    }
}

__device__ __forceinline__ void ld_tile128(bf16* sm, const bf16* gp, size_t ldg, int tid) {
    const int r = tid >> 2, c = (tid & 3) * 8;
    cp16(sm + r*40 + c,      gp + (size_t)r * ldg + c);
    cp16(sm + (r+64)*40 + c, gp + (size_t)(r+64) * ldg + c);
}

// ---------------- conversion kernels ----------------
// fp32 [M,K] -> bf16 [M,3K] = [hi | hi | lo]
__global__ __launch_bounds__(256) void split_rows(
    const float* __restrict__ in, bf16* __restrict__ out, int K)
{
    int id = blockIdx.x * 256 + threadIdx.x;
    int kq = K >> 2;
    int row = id / kq, c4 = id - row * kq;
    float4 v = ((const float4*)in)[(size_t)row * kq + c4];
    bf16 h0,h1,h2,h3,l0,l1,l2,l3;
    split1(v.x,h0,l0); split1(v.y,h1,l1); split1(v.z,h2,l2); split1(v.w,h3,l3);
    uint2 hp = {bpack(h0,h1), bpack(h2,h3)};
    uint2 lp = {bpack(l0,l1), bpack(l2,l3)};
    size_t base = (size_t)row * 3 * K + c4 * 4;
    *(uint2*)(out + base)       = hp;
    *(uint2*)(out + base + K)   = hp;
    *(uint2*)(out + base + 2*K) = lp;
}

// fp32 W[K,N] -> bf16 Wt[N,3K] = [hi | lo | hi]  (transposed)
__global__ void split_wt(const float* __restrict__ W, bf16* __restrict__ Wt,
                         int K, int N)
{
    __shared__ float t[32][33];
    int k0 = blockIdx.y * 32, n0 = blockIdx.x * 32;
    int tx = threadIdx.x, ty = threadIdx.y;
    #pragma unroll
    for (int j = 0; j < 4; j++)
        t[ty + j*8][tx] = W[(size_t)(k0 + ty + j*8) * N + n0 + tx];
    __syncthreads();
    int K3 = 3 * K;
    #pragma unroll
    for (int j = 0; j < 4; j++) {
        int n = n0 + ty + j*8, k = k0 + tx;
        bf16 h, l; split1(t[tx][ty + j*8], h, l);
        Wt[(size_t)n*K3 + k]       = h;
        Wt[(size_t)n*K3 + K + k]   = l;
        Wt[(size_t)n*K3 + 2*K + k] = h;
    }
}

// fp32 [b*S+q][h*64+d] -> bf16 [bh][q][192]; side0=[hi,hi,lo] side1=[hi,lo,hi]
__global__ __launch_bounds__(256) void split_qk(
    const float* __restrict__ in, bf16* __restrict__ out, int side)
{
    int id = blockIdx.x * 256 + threadIdx.x;
    int row = id >> 8, c4 = id & 255;
    float4 v = ((const float4*)in)[(size_t)row * 256 + c4];
    int col = c4 * 4, h = col >> 6, d = col & 63;
    int b = row >> 11, q = row & 2047;
    bf16 h0,h1,h2,h3,l0,l1,l2,l3;
    split1(v.x,h0,l0); split1(v.y,h1,l1); split1(v.z,h2,l2); split1(v.w,h3,l3);
    uint2 hp = {bpack(h0,h1), bpack(h2,h3)};
    uint2 lp = {bpack(l0,l1), bpack(l2,l3)};
    size_t base = ((size_t)((b*NH + h)*S + q)) * 192 + d;
    if (side == 0) {
        *(uint2*)(out + base)       = hp;
        *(uint2*)(out + base + 64)  = hp;
        *(uint2*)(out + base + 128) = lp;
    } else {
        *(uint2*)(out + base)       = hp;
        *(uint2*)(out + base + 64)  = lp;
        *(uint2*)(out + base + 128) = hp;
    }
}

// fp32 V [b*S+k][h*64+d] -> bf16 Vs[bh][d][3*2048] = [hi | lo | hi]
__global__ void split_v(const float* __restrict__ v, bf16* __restrict__ vs)
{
    __shared__ float t[32][33];
    int k0 = blockIdx.x * 32, d0 = blockIdx.y * 32, bh = blockIdx.z;
    int b = bh >> 4, h = bh & 15;
    int tx = threadIdx.x, ty = threadIdx.y;
    #pragma unroll
    for (int j = 0; j < 4; j++)
        t[ty + j*8][tx] = v[(size_t)(b*S + k0 + ty + j*8)*DM + h*64 + d0 + tx];
    __syncthreads();
    #pragma unroll
    for (int j = 0; j < 4; j++) {
        int d = d0 + ty + j*8, k = k0 + tx;
        bf16 hi, lo; split1(t[tx][ty + j*8], hi, lo);
        size_t base = ((size_t)bh*64 + d) * (3*S) + k;
        vs[base]       = hi;
        vs[base + S]   = lo;
        vs[base + 2*S] = hi;
    }
}

// ---------------- dense GEMM: C[M,N] = A'[M,3K] . Wt'[N,3K]^T + bias ------
__global__ __launch_bounds__(256) void hgemm_bias(
    const bf16* __restrict__ A, const bf16* __restrict__ Bt,
    const float* __restrict__ bias, float* __restrict__ C,
    int Nd, int K3, int relu)
{
    __shared__ bf16 As[2][128*40];
    __shared__ bf16 Bs[2][128*40];
    const int tid = threadIdx.x, lane = tid & 31, warp = tid >> 5;
    const int wm = warp >> 2, wn = warp & 3;
    const int m0 = blockIdx.y * 128, n0 = blockIdx.x * 128;
    const bf16* Ag = A  + (size_t)m0 * K3;
    const bf16* Bg = Bt + (size_t)n0 * K3;
    float acc[4][4][4] = {};
    const int KT = K3 >> 5;

    ld_tile128(As[0], Ag, K3, tid);
    ld_tile128(Bs[0], Bg, K3, tid);
    CP_COMMIT;
    for (int kt = 0; kt < KT; kt++) {
        CP_WAIT0; __syncthreads();
        if (kt + 1 < KT) {
            const int st = (kt + 1) & 1;
            ld_tile128(As[st], Ag + (size_t)(kt+1)*32, K3, tid);
            ld_tile128(Bs[st], Bg + (size_t)(kt+1)*32, K3, tid);
            CP_COMMIT;
        }
        wmma_ks<4,4,40>(&As[kt&1][wm*64*40], &Bs[kt&1][wn*32*40], lane, acc);
    }

    const int g = lane >> 2, t2 = (lane & 3) * 2;
    #pragma unroll
    for (int mi = 0; mi < 4; mi++)
        #pragma unroll
        for (int ni = 0; ni < 4; ni++) {
            const int r = m0 + wm*64 + mi*16 + g;
            const int c = n0 + wn*32 + ni*8 + t2;
            float2 bv = *(const float2*)(bias + c);
            float2 o1 = {acc[mi][ni][0] + bv.x, acc[mi][ni][1] + bv.y};
            float2 o2 = {acc[mi][ni][2] + bv.x, acc[mi][ni][3] + bv.y};
            if (relu) {
                o1.x = fmaxf(o1.x, 0.f); o1.y = fmaxf(o1.y, 0.f);
                o2.x = fmaxf(o2.x, 0.f); o2.y = fmaxf(o2.y, 0.f);
            }
            *(float2*)(C + (size_t)r*Nd + c)     = o1;
            *(float2*)(C + (size_t)(r+8)*Nd + c) = o2;
        }
}

// ---------------- fused flash attention ------------------------------------
// MODE 0: lookahead mask [B,1,S,S], no logits output
// MODE 1: padding mask [B,1,1,S], writes raw logits tiles to lg (fp32)
// q-tile 128, k-chunks of 64, 8 warps x 16 q rows, online softmax,
// P hi/lo split 3-term PV (Ph.Vh + Pl.Vh + Ph.Vl) in registers.
template<int MODE>
__global__ __launch_bounds__(256, 2) void flash_attn(
    const bf16* __restrict__ Qg, const bf16* __restrict__ Kg,
    const bf16* __restrict__ Vg, const float* __restrict__ mask,
    float* __restrict__ lg, float* __restrict__ ctx)
{
    extern __shared__ bf16 sm[];
    bf16* Qs = sm;                      // [128][200]
    bf16* Ks = sm + 128*200;            // [64][200]
    bf16* Vt = sm + 128*200 + 64*200;   // [64][136]: hi cols 0-63, lo 64-127

    const int tid = threadIdx.x, lane = tid & 31, warp = tid >> 5;
    const int g = lane >> 2, t2 = (lane & 3) * 2;
    const int bh = blockIdx.y, b = bh >> 4, h = bh & 15;
    const int q0 = blockIdx.x * 128;
    const int qr = q0 + warp*16 + g;    // this thread's row (and qr+8)

    // load Q tile once: 128 x 192
    {
        const bf16* src = Qg + ((size_t)bh*S + q0) * 192;
        const int r = tid >> 1, cb = (tid & 1) * 8;
        #pragma unroll
        for (int i = 0; i < 12; i++)
            cp16(Qs + r*200 + cb + i*16, src + (size_t)r*192 + cb + i*16);
    }
    CP_COMMIT; CP_WAIT0; __syncthreads();

    float m_lo = -INFINITY, m_hi = -INFINITY, l_lo = 0.f, l_hi = 0.f;
    float acc_o[8][4] = {};

    for (int k0 = 0; k0 < S; k0 += 64) {
        __syncthreads();
        // K chunk 64 x 192
        {
            const int r = tid >> 2, cb = (tid & 3) * 8;
            const bf16* src = Kg + ((size_t)bh*S + k0 + r) * 192;
            #pragma unroll
            for (int i = 0; i < 6; i++)
                cp16(Ks + r*200 + cb + i*32, src + cb + i*32);
        }
        // V chunk: Vt[d][0..63]=hi(k0 window), [64..127]=lo
        {
            const int d = tid >> 2;
            const bf16* vb = Vg + ((size_t)bh*64 + d) * (3*S);
            #pragma unroll
            for (int i = 0; i < 4; i++) {
                const int j = (tid & 3) + i*4;                // 0..15
                const int src = (j < 8) ? (k0 + j*8) : (S + k0 + (j-8)*8);
                cp16(Vt + d*136 + j*8, vb + src);
            }
        }
        CP_COMMIT; CP_WAIT0; __syncthreads();

        // scores 128x64: per warp 16q x 64k
        float sacc[1][8][4] = {};
        #pragma unroll
        for (int kc = 0; kc < 6; kc++)
            wmma_ks<1,8,200>(Qs + (warp*16)*200 + kc*32, Ks + kc*32, lane, sacc);

        // scale + mask (+ logits out), tile max
        float mt_lo = -INFINITY, mt_hi = -INFINITY;
        #pragma unroll
        for (int ni = 0; ni < 8; ni++) {
            const int kk = k0 + ni*8 + t2;
            float2 mA, mB;
            if (MODE == 0) {
                mA = *(const float2*)(mask + ((size_t)b*S + qr)*S + kk);
                mB = *(const float2*)(mask + ((size_t)b*S + qr + 8)*S + kk);
            } else {
                mA = *(const float2*)(mask + (size_t)b*S + kk);
                mB = mA;
            }
            sacc[0][ni][0] = sacc[0][ni][0]*0.125f + mA.x*(-1e9f);
            sacc[0][ni][1] = sacc[0][ni][1]*0.125f + mA.y*(-1e9f);
            sacc[0][ni][2] = sacc[0][ni][2]*0.125f + mB.x*(-1e9f);
            sacc[0][ni][3] = sacc[0][ni][3]*0.125f + mB.y*(-1e9f);
            if (MODE == 1) {
                *(float2*)(lg + ((size_t)bh*S + qr)*S + kk) =
                    make_float2(sacc[0][ni][0], sacc[0][ni][1]);
                *(float2*)(lg + ((size_t)bh*S + qr + 8)*S + kk) =
                    make_float2(sacc[0][ni][2], sacc[0][ni][3]);
            }
            mt_lo = fmaxf(mt_lo, fmaxf(sacc[0][ni][0], sacc[0][ni][1]));
            mt_hi = fmaxf(mt_hi, fmaxf(sacc[0][ni][2], sacc[0][ni][3]));
        }
        #pragma unroll
        for (int off = 1; off <= 2; off <<= 1) {
            mt_lo = fmaxf(mt_lo, __shfl_xor_sync(~0u, mt_lo, off));
            mt_hi = fmaxf(mt_hi, __shfl_xor_sync(~0u, mt_hi, off));
        }
        const float mn_lo = fmaxf(m_lo, mt_lo), mn_hi = fmaxf(m_hi, mt_hi);
        const float al_lo = __expf(m_lo - mn_lo), al_hi = __expf(m_hi - mn_hi);
        m_lo = mn_lo; m_hi = mn_hi;

        // p = exp(s - m), build A fragments (hi & lo), row sums
        unsigned pa_h[4][4], pa_l[4][4];
        float rs_lo = 0.f, rs_hi = 0.f;
        #pragma unroll
        for (int ni = 0; ni < 8; ni++) {
            float p0 = __expf(sacc[0][ni][0] - mn_lo);
            float p1 = __expf(sacc[0][ni][1] - mn_lo);
            float p2 = __expf(sacc[0][ni][2] - mn_hi);
            float p3 = __expf(sacc[0][ni][3] - mn_hi);
            rs_lo += p0 + p1; rs_hi += p2 + p3;
            bf16 h0,l0,h1,l1,h2,l2,h3,l3;
            split1(p0,h0,l0); split1(p1,h1,l1); split1(p2,h2,l2); split1(p3,h3,l3);
            const int j = ni >> 1;
            if ((ni & 1) == 0) {
                pa_h[j][0] = bpack(h0,h1); pa_h[j][1] = bpack(h2,h3);
                pa_l[j][0] = bpack(l0,l1); pa_l[j][1] = bpack(l2,l3);
            } else {
                pa_h[j][2] = bpack(h0,h1); pa_h[j][3] = bpack(h2,h3);
                pa_l[j][2] = bpack(l0,l1); pa_l[j][3] = bpack(l2,l3);
            }
        }
        #pragma unroll
        for (int off = 1; off <= 2; off <<= 1) {
            rs_lo += __shfl_xor_sync(~0u, rs_lo, off);
            rs_hi += __shfl_xor_sync(~0u, rs_hi, off);
        }
        l_lo = l_lo*al_lo + rs_lo; l_hi = l_hi*al_hi + rs_hi;

        // rescale accumulator
        #pragma unroll
        for (int nd = 0; nd < 8; nd++) {
            acc_o[nd][0] *= al_lo; acc_o[nd][1] *= al_lo;
            acc_o[nd][2] *= al_hi; acc_o[nd][3] *= al_hi;
        }
        // PV: 3-term
        #pragma unroll
        for (int j = 0; j < 4; j++)
            #pragma unroll
            for (int nd = 0; nd < 8; nd++) {
                const bf16* pv = Vt + (nd*8 + g)*136 + j*16 + t2;
                unsigned bh2[2], bl2[2];
                bh2[0] = *(const unsigned*)pv;        bh2[1] = *(const unsigned*)(pv + 8);
                bl2[0] = *(const unsigned*)(pv + 64); bl2[1] = *(const unsigned*)(pv + 72);
                mma16816(acc_o[nd], pa_h[j], bh2);
                mma16816(acc_o[nd], pa_l[j], bh2);
                mma16816(acc_o[nd], pa_h[j], bl2);
            }
    }

    // epilogue: ctx[b, q, h*64+d] = acc / l
    const float il_lo = 1.f / l_lo, il_hi = 1.f / l_hi;
    #pragma unroll
    for (int nd = 0; nd < 8; nd++) {
        const int d = nd*8 + t2;
        size_t base = ((size_t)b*S + qr)*DM + h*64 + d;
        *(float2*)(ctx + base)        = make_float2(acc_o[nd][0]*il_lo, acc_o[nd][1]*il_lo);
        *(float2*)(ctx + base + 8*DM) = make_float2(acc_o[nd][2]*il_hi, acc_o[nd][3]*il_hi);
    }
}

// ---------------- fused residual add + LayerNorm --------------------------
__global__ __launch_bounds__(256) void add_ln_kernel(
    const float* __restrict__ a, const float* __restrict__ bres,
    const float* __restrict__ g, const float* __restrict__ beta,
    float* __restrict__ out)
{
    const size_t row = blockIdx.x;
    const float* pa = a + row * DM;
    const float* pb = bres + row * DM;
    const int tid = threadIdx.x, lane = tid & 31, warp = tid >> 5;
    __shared__ float rs1[8], rs2[8];

    float x[4];
    float s = 0.f, s2 = 0.f;
    #pragma unroll
    for (int i = 0; i < 4; i++) {
        float t = pa[tid + i*256] + pb[tid + i*256];
        x[i] = t; s += t; s2 += t * t;
    }
    #pragma unroll
    for (int off = 16; off; off >>= 1) {
        s  += __shfl_xor_sync(~0u, s, off);
        s2 += __shfl_xor_sync(~0u, s2, off);
    }
    if (lane == 0) { rs1[warp] = s; rs2[warp] = s2; }
    __syncthreads();
    s = 0.f; s2 = 0.f;
    #pragma unroll
    for (int w = 0; w < 8; w++) { s += rs1[w]; s2 += rs2[w]; }
    const float mu = s * (1.f / DM);
    const float var = s2 * (1.f / DM) - mu * mu;
    const float inv = rsqrtf(var + EPS);
    #pragma unroll
    for (int i = 0; i < 4; i++) {
        const int col = tid + i*256;
        out[row*DM + col] = (x[i] - mu) * inv * g[col] + beta[col];
    }
}

// ------------------------------- launch -----------------------------------
extern "C" void kernel_launch(void* const* d_in, const int* in_sizes, int n_in,
                              void* d_out, int out_size)
{
    const float* x    = (const float*)d_in[0];
    const float* enc  = (const float*)d_in[1];
    const float* lam  = (const float*)d_in[2];
    const float* pm   = (const float*)d_in[3];
    const float* wq1  = (const float*)d_in[4];  const float* bq1 = (const float*)d_in[5];
    const float* wk1  = (const float*)d_in[6];  const float* bk1 = (const float*)d_in[7];
    const float* wv1  = (const float*)d_in[8];  const float* bv1 = (const float*)d_in[9];
    const float* wo1  = (const float*)d_in[10]; const float* bo1 = (const float*)d_in[11];
    const float* wq2  = (const float*)d_in[12]; const float* bq2 = (const float*)d_in[13];
    const float* wk2  = (const float*)d_in[14]; const float* bk2 = (const float*)d_in[15];
    const float* wv2  = (const float*)d_in[16]; const float* bv2 = (const float*)d_in[17];
    const float* wo2  = (const float*)d_in[18]; const float* bo2 = (const float*)d_in[19];
    const float* wf1  = (const float*)d_in[20]; const float* bf1 = (const float*)d_in[21];
    const float* wf2  = (const float*)d_in[22]; const float* bf2 = (const float*)d_in[23];
    const float* ln2g = (const float*)d_in[24]; const float* ln2b = (const float*)d_in[25];
    const float* ln3g = (const float*)d_in[26]; const float* ln3b = (const float*)d_in[27];

    float* out3    = (float*)d_out;
    float* logits2 = (float*)d_out + (size_t)MT * DM;

    float *q, *k, *v, *ctx, *out1, *out2, *tmp, *ffn;
    bf16 *ab, *wt, *qs, *ks, *vs;
    cudaGetSymbolAddress((void**)&q,    g_q);
    cudaGetSymbolAddress((void**)&k,    g_k);
    cudaGetSymbolAddress((void**)&v,    g_v);
    cudaGetSymbolAddress((void**)&ctx,  g_ctx);
    cudaGetSymbolAddress((void**)&out1, g_out1);
    cudaGetSymbolAddress((void**)&out2, g_out2);
    cudaGetSymbolAddress((void**)&tmp,  g_tmp);
    cudaGetSymbolAddress((void**)&ffn,  g_ffn);
    cudaGetSymbolAddress((void**)&ab,   g_ab);
    cudaGetSymbolAddress((void**)&wt,   g_wt);
    cudaGetSymbolAddress((void**)&qs,   g_qs);
    cudaGetSymbolAddress((void**)&ks,   g_ks);
    cudaGetSymbolAddress((void**)&vs,   g_vs);

    const dim3 tWT(32, 8);
    const dim3 gWT_dd(DM/32, DM/32);
    const dim3 gWT_df(DFF/32, DM/32);
    const dim3 gWT_fd(DM/32, DFF/32);
    const dim3 gG_d(DM/128, MT/128);
    const dim3 gG_f(DFF/128, MT/128);
    const dim3 gFA(S/128, BH);
    const dim3 gSV(S/32, DP/32, BH);
    const int nSR_d = MT*DM/1024;
    const int nSR_f = (int)((size_t)MT*DFF/1024);
    const size_t faSmem = (size_t)(128*200 + 64*200 + 64*136) * sizeof(bf16);
    cudaFuncSetAttribute(flash_attn<0>, cudaFuncAttributeMaxDynamicSharedMemorySize, (int)faSmem);
    cudaFuncSetAttribute(flash_attn<1>, cudaFuncAttributeMaxDynamicSharedMemorySize, (int)faSmem);

    // ===== MHA1 =====
    split_rows<<<nSR_d, 256>>>(x, ab, DM);
    split_wt<<<gWT_dd, tWT>>>(wq1, wt, DM, DM);
    hgemm_bias<<<gG_d, 256>>>(ab, wt, bq1, q, DM, 3*DM, 0);
    split_wt<<<gWT_dd, tWT>>>(wk1, wt, DM, DM);
    hgemm_bias<<<gG_d, 256>>>(ab, wt, bk1, k, DM, 3*DM, 0);
    split_wt<<<gWT_dd, tWT>>>(wv1, wt, DM, DM);
    hgemm_bias<<<gG_d, 256>>>(ab, wt, bv1, v, DM, 3*DM, 0);
    split_qk<<<MT, 256>>>(q, qs, 0);
    split_qk<<<MT, 256>>>(k, ks, 1);
    split_v<<<gSV, tWT>>>(v, vs);
    flash_attn<0><<<gFA, 256, faSmem>>>(qs, ks, vs, lam, nullptr, ctx);
    split_rows<<<nSR_d, 256>>>(ctx, ab, DM);
    split_wt<<<gWT_dd, tWT>>>(wo1, wt, DM, DM);
    hgemm_bias<<<gG_d, 256>>>(ab, wt, bo1, out1, DM, 3*DM, 0);

    // ===== MHA2 (raw logits2 -> d_out) =====
    split_rows<<<nSR_d, 256>>>(out1, ab, DM);
    split_wt<<<gWT_dd, tWT>>>(wq2, wt, DM, DM);
    hgemm_bias<<<gG_d, 256>>>(ab, wt, bq2, q, DM, 3*DM, 0);
    split_rows<<<nSR_d, 256>>>(enc, ab, DM);
    split_wt<<<gWT_dd, tWT>>>(wk2, wt, DM, DM);
    hgemm_bias<<<gG_d, 256>>>(ab, wt, bk2, k, DM, 3*DM, 0);
    split_wt<<<gWT_dd, tWT>>>(wv2, wt, DM, DM);
    hgemm_bias<<<gG_d, 256>>>(ab, wt, bv2, v, DM, 3*DM, 0);
    split_qk<<<MT, 256>>>(q, qs, 0);
    split_qk<<<MT, 256>>>(k, ks, 1);
    split_v<<<gSV, tWT>>>(v, vs);
    flash_attn<1><<<gFA, 256, faSmem>>>(qs, ks, vs, pm, logits2, ctx);
    split_rows<<<nSR_d, 256>>>(ctx, ab, DM);
    split_wt<<<gWT_dd, tWT>>>(wo2, wt, DM, DM);
    hgemm_bias<<<gG_d, 256>>>(ab, wt, bo2, tmp, DM, 3*DM, 0);
    add_ln_kernel<<<MT, 256>>>(tmp, out1, ln2g, ln2b, out2);

    // ===== FFN =====
    split_rows<<<nSR_d, 256>>>(out2, ab, DM);
    split_wt<<<gWT_df, tWT>>>(wf1, wt, DM, DFF);
    hgemm_bias<<<gG_f, 256>>>(ab, wt, bf1, ffn, DFF, 3*DM, 1);
    split_rows<<<nSR_f, 256>>>(ffn, ab, DFF);
    split_wt<<<gWT_fd, tWT>>>(wf2, wt, DFF, DM);
    hgemm_bias<<<gG_d, 256>>>(ab, wt, bf2, tmp, DM, 3*DFF, 0);
    add_ln_kernel<<<MT, 256>>>(tmp, out2, ln3g, ln3b, out3);
}